// round 12
// baseline (speedup 1.0000x reference)
#include <cuda_runtime.h>

// Reference math:
//   y = x @ W.T + b                      (B, OUT)
//   m = max(y, axis=1, keepdims=True)    (B, 1)
//   centered = m - mean(m, axis=1)       == 0 exactly (mean over a size-1 axis)
//   out = gelu_tanh(0)                   == 0 exactly  (tanh-GELU of 0 is 0)
//
// Output is identically zero for ALL inputs; the 137-GFLOP GEMM is dead code.
// Fastest correct kernel = one graph node writing 4096 zero floats (16 KB).
//
// Config search + noise calibration (R3/R8/R11 ran THIS exact source):
//   R3/R8/R11 1x1024, 1 st/thr : kernel 3.136/3.520/3.104us | e2e 4.608/4.928/4.576us
//   R1  4 CTA x 256            : kernel 3.424us
//   R6  1 CTA x 128, 8 st/thr  : kernel 3.712us
//   R2  graph memset node      : 5.12us e2e (real regression — driver path)
// => noise band ±0.4us; all kernel-node shapes indistinguishable; memset node
//    strictly worse. ncu: DRAM 0.0%, L2 0.3%, all pipes 0.0%. Remaining time
//    is fixed single-node dispatch + graph-replay overhead, not addressable
//    from the .cu. TERMINAL KERNEL — converged; do not perturb for noise.

__global__ void __launch_bounds__(1024, 1)
ModelNew_25056839205334_zero(float4* __restrict__ out) {
    // out_size = 4096 floats = 1024 float4; exactly one STG.128 per thread.
    out[threadIdx.x] = make_float4(0.0f, 0.0f, 0.0f, 0.0f);
}

extern "C" void kernel_launch(void* const* d_in, const int* in_sizes, int n_in,
                              void* d_out, int out_size) {
    (void)d_in; (void)in_sizes; (void)n_in;
    if (out_size == 4096) {
        ModelNew_25056839205334_zero<<<1, 1024>>>((float4*)d_out);
    } else {
        // Generic fallback (never taken for this problem's fixed shape).
        cudaMemsetAsync(d_out, 0, (size_t)out_size * sizeof(float), 0);
    }
}

// round 13
// speedup vs baseline: 1.0132x; 1.0132x over previous
#include <cuda_runtime.h>

// Reference math:
//   y = x @ W.T + b                      (B, OUT)
//   m = max(y, axis=1, keepdims=True)    (B, 1)
//   centered = m - mean(m, axis=1)       == 0 exactly (mean over a size-1 axis)
//   out = gelu_tanh(0)                   == 0 exactly  (tanh-GELU of 0 is 0)
//
// Output is identically zero for ALL inputs; the 137-GFLOP GEMM is dead code.
// Fastest correct kernel = one graph node writing 4096 zero floats (16 KB).
//
// Config search + noise calibration (R3/R8/R11/R12 ran THIS exact source):
//   1x1024, 1 st/thr : kernel {3.104, 3.136, 3.520, 3.808}us
//                      e2e    {4.576, 4.608, 4.928, 4.928}us
//   R1  4 CTA x 256            : kernel 3.424us   (within noise)
//   R6  1 CTA x 128, 8 st/thr  : kernel 3.712us   (within noise)
//   R2  graph memset node      : 5.12us e2e       (real regression)
// => ±0.4us environmental noise; kernel-node shapes indistinguishable; memset
//    node strictly worse. ncu: DRAM 0.0%, all pipes 0.0%, L2 0.3%. Remaining
//    time is fixed single-node dispatch + graph-replay overhead, not
//    addressable from the .cu. TERMINAL KERNEL — converged; holding.

__global__ void __launch_bounds__(1024, 1)
ModelNew_25056839205334_zero(float4* __restrict__ out) {
    // out_size = 4096 floats = 1024 float4; exactly one STG.128 per thread.
    out[threadIdx.x] = make_float4(0.0f, 0.0f, 0.0f, 0.0f);
}

extern "C" void kernel_launch(void* const* d_in, const int* in_sizes, int n_in,
                              void* d_out, int out_size) {
    (void)d_in; (void)in_sizes; (void)n_in;
    if (out_size == 4096) {
        ModelNew_25056839205334_zero<<<1, 1024>>>((float4*)d_out);
    } else {
        // Generic fallback (never taken for this problem's fixed shape).
        cudaMemsetAsync(d_out, 0, (size_t)out_size * sizeof(float), 0);
    }
}

// round 14
// speedup vs baseline: 1.0694x; 1.0556x over previous
#include <cuda_runtime.h>

// Reference math:
//   y = x @ W.T + b                      (B, OUT)
//   m = max(y, axis=1, keepdims=True)    (B, 1)
//   centered = m - mean(m, axis=1)       == 0 exactly (mean over a size-1 axis)
//   out = gelu_tanh(0)                   == 0 exactly  (tanh-GELU of 0 is 0)
//
// Output is identically zero for ALL inputs; the 137-GFLOP GEMM is dead code.
// Fastest correct kernel = one graph node writing 4096 zero floats (16 KB).
//
// Noise calibration — R3/R8/R11/R12/R13 all ran THIS exact source:
//   e2e    {4.576, 4.608, 4.864, 4.928, 4.928}us
//   kernel {3.104, 3.136, 3.520, 3.808, 3.968}us  (drift = DVFS/thermal)
// Alternatives, all ruled out:
//   R1  4 CTA x 256            : kernel 3.424us   (within noise)
//   R6  1 CTA x 128, 8 st/thr  : kernel 3.712us   (within noise)
//   R2  graph memset node      : 5.12us e2e       (real regression)
// ncu: DRAM 0.0%, all pipes 0.0%, L2 0.3%, regs=16, smem=0 — no throughput
// axis; measured time is single-node dispatch + graph-replay fixed cost.
// TERMINAL KERNEL — converged; holding the measured optimum.

__global__ void __launch_bounds__(1024, 1)
ModelNew_25056839205334_zero(float4* __restrict__ out) {
    // out_size = 4096 floats = 1024 float4; exactly one STG.128 per thread.
    out[threadIdx.x] = make_float4(0.0f, 0.0f, 0.0f, 0.0f);
}

extern "C" void kernel_launch(void* const* d_in, const int* in_sizes, int n_in,
                              void* d_out, int out_size) {
    (void)d_in; (void)in_sizes; (void)n_in;
    if (out_size == 4096) {
        ModelNew_25056839205334_zero<<<1, 1024>>>((float4*)d_out);
    } else {
        // Generic fallback (never taken for this problem's fixed shape).
        cudaMemsetAsync(d_out, 0, (size_t)out_size * sizeof(float), 0);
    }
}